// round 2
// baseline (speedup 1.0000x reference)
#include <cuda_runtime.h>
#include <cstdint>

#define S 2048
#define B 32
#define I 256
#define H 256
#define G4 1024
#define NCTA 128
#define NTHR 128

// Static device scratch (no cudaMalloc allowed).
__device__ float g_Wp[I * G4];                 // packed/permuted input weights  [k][colp]
__device__ float g_Up[H * G4];                 // packed/permuted recurrent wts  [k][colp]
__device__ float g_bp[G4];                     // packed bias
__device__ float g_xg[(size_t)S * B * G4];     // precomputed input projections [t][b][colp]  (256 MB)
__device__ float g_hbuf[2][H * B];             // ping-pong h broadcast  [parity][dim][b]
__device__ unsigned g_ctr[S];                  // per-step arrival counters

// colp = cta*8 + g*2 + dd  maps to gate g in {f,i,c,o} and hidden dim j = 2*cta + dd
__global__ void pack_kernel(
    const float* __restrict__ Wf, const float* __restrict__ Wi,
    const float* __restrict__ Wc, const float* __restrict__ Wo,
    const float* __restrict__ Uf, const float* __restrict__ Ui,
    const float* __restrict__ Uc, const float* __restrict__ Uo,
    const float* __restrict__ bf, const float* __restrict__ bi,
    const float* __restrict__ bc, const float* __restrict__ bo)
{
    int idx = blockIdx.x * blockDim.x + threadIdx.x;
    if (idx < I * G4) {
        int k    = idx >> 10;
        int colp = idx & 1023;
        int g    = (colp >> 1) & 3;
        int j    = ((colp >> 3) << 1) | (colp & 1);
        const float* W = (g == 0) ? Wf : (g == 1) ? Wi : (g == 2) ? Wc : Wo;
        const float* U = (g == 0) ? Uf : (g == 1) ? Ui : (g == 2) ? Uc : Uo;
        g_Wp[idx] = W[k * H + j];
        g_Up[idx] = U[k * H + j];
        if (k == 0) {
            const float* bv = (g == 0) ? bf : (g == 1) ? bi : (g == 2) ? bc : bo;
            g_bp[colp] = bv[j];
        }
    }
    if (idx < 2 * H * B) ((float*)g_hbuf)[idx] = 0.f;
    if (idx < S) g_ctr[idx] = 0u;
}

// ---------------- Phase 1: xg[t][b][colp] = x[b][t][:] @ Wp + bp ----------------
#define BM 64
#define BN 64
#define BK 16

__global__ __launch_bounds__(256) void gemm_xg_kernel(const float* __restrict__ x)
{
    __shared__ float As[BK][BM + 4];   // transposed A tile, padded
    __shared__ float Bs[BK][BN];

    int tid = threadIdx.x;
    int r0 = blockIdx.y * BM;   // rows r = t*B + b
    int c0 = blockIdx.x * BN;
    int tr = tid >> 4, tc = tid & 15;

    int aRow = tid >> 2;
    int aK   = (tid & 3) << 2;
    int bK   = tid >> 4;
    int bC   = (tid & 15) << 2;

    int r  = r0 + aRow;
    int bb = r & 31;
    int tt = r >> 5;
    const float* aptr = x + ((size_t)bb * S + tt) * I + aK;

    float acc[4][4];
#pragma unroll
    for (int i2 = 0; i2 < 4; ++i2)
#pragma unroll
        for (int j2 = 0; j2 < 4; ++j2) acc[i2][j2] = 0.f;

    for (int k0 = 0; k0 < I; k0 += BK) {
        float4 av = *(const float4*)(aptr + k0);
        As[aK + 0][aRow] = av.x;
        As[aK + 1][aRow] = av.y;
        As[aK + 2][aRow] = av.z;
        As[aK + 3][aRow] = av.w;
        float4 bv = *(const float4*)(g_Wp + (size_t)(k0 + bK) * G4 + c0 + bC);
        *(float4*)&Bs[bK][bC] = bv;
        __syncthreads();
#pragma unroll
        for (int kk = 0; kk < BK; ++kk) {
            float4 a4 = *(const float4*)&As[kk][tr << 2];
            float4 b4 = *(const float4*)&Bs[kk][tc << 2];
            acc[0][0] = fmaf(a4.x, b4.x, acc[0][0]);
            acc[0][1] = fmaf(a4.x, b4.y, acc[0][1]);
            acc[0][2] = fmaf(a4.x, b4.z, acc[0][2]);
            acc[0][3] = fmaf(a4.x, b4.w, acc[0][3]);
            acc[1][0] = fmaf(a4.y, b4.x, acc[1][0]);
            acc[1][1] = fmaf(a4.y, b4.y, acc[1][1]);
            acc[1][2] = fmaf(a4.y, b4.z, acc[1][2]);
            acc[1][3] = fmaf(a4.y, b4.w, acc[1][3]);
            acc[2][0] = fmaf(a4.z, b4.x, acc[2][0]);
            acc[2][1] = fmaf(a4.z, b4.y, acc[2][1]);
            acc[2][2] = fmaf(a4.z, b4.z, acc[2][2]);
            acc[2][3] = fmaf(a4.z, b4.w, acc[2][3]);
            acc[3][0] = fmaf(a4.w, b4.x, acc[3][0]);
            acc[3][1] = fmaf(a4.w, b4.y, acc[3][1]);
            acc[3][2] = fmaf(a4.w, b4.z, acc[3][2]);
            acc[3][3] = fmaf(a4.w, b4.w, acc[3][3]);
        }
        __syncthreads();
    }

    float4 bias = *(const float4*)&g_bp[c0 + (tc << 2)];
#pragma unroll
    for (int i2 = 0; i2 < 4; ++i2) {
        int rr = r0 + (tr << 2) + i2;
        float4 o;
        o.x = acc[i2][0] + bias.x;
        o.y = acc[i2][1] + bias.y;
        o.z = acc[i2][2] + bias.z;
        o.w = acc[i2][3] + bias.w;
        *(float4*)(g_xg + (size_t)rr * G4 + c0 + (tc << 2)) = o;
    }
}

// ---------------- Phase 2: persistent recurrence ----------------
__device__ __forceinline__ float sigmoidf_(float v) {
    return 1.f / (1.f + __expf(-v));
}

__global__ __launch_bounds__(NTHR, 1) void lstm_kernel(float* __restrict__ out, int out_size)
{
    int cta = blockIdx.x;
    int tid = threadIdx.x;
    int bgrp = tid >> 4;     // 0..7 -> batches 4*bgrp..+3
    int ks   = tid & 15;     // k-slice: k = it*16 + ks

    __shared__ float U_s[8][H];        // [c][k], c = local gate col
    __shared__ float red[8][32][17];   // partials [c][b][ks], padded (stride 17 -> conflict-free)
    __shared__ float z_s[8][32];

    for (int i = tid; i < 8 * H; i += NTHR) {
        int c = i >> 8, k = i & 255;
        U_s[c][k] = g_Up[(size_t)k * G4 + cta * 8 + c];
    }

    int dd = tid >> 5;       // for update threads (tid<64)
    int bb = tid & 31;
    int c1 = tid >> 5;       // for reduction outputs o=tid, o=tid+128
    float cstate = 0.f;
    __syncthreads();

    for (int t = 0; t < S; ++t) {
        if (t > 0) {
            if (tid == 0) {
                volatile unsigned* p = &g_ctr[t - 1];
                while (*p < NCTA) {}
                __threadfence();   // acquire: order subsequent h loads after observed release
            }
            __syncthreads();
        }

        // prefetch this step's input projections (1 sector per batch row)
        const float* xgp = g_xg + (size_t)t * (B * G4) + cta * 8;
        float xv1 = __ldg(xgp + (size_t)bb * G4 + c1);
        float xv2 = __ldg(xgp + (size_t)bb * G4 + c1 + 4);

        // prefetch h_{t-1} (bypass L1: incoherent across SMs)
        const float4* hb = (const float4*)g_hbuf[(t + 1) & 1];
        float4 hv[16];
#pragma unroll
        for (int it = 0; it < 16; ++it)
            hv[it] = __ldcg(hb + (size_t)(it * 16 + ks) * 8 + bgrp);

        float acc[8][4];
#pragma unroll
        for (int c = 0; c < 8; ++c)
#pragma unroll
            for (int q = 0; q < 4; ++q) acc[c][q] = 0.f;

#pragma unroll
        for (int it = 0; it < 16; ++it) {
            int k = it * 16 + ks;
            float4 h4 = hv[it];
#pragma unroll
            for (int c = 0; c < 8; ++c) {
                float u = U_s[c][k];
                acc[c][0] = fmaf(u, h4.x, acc[c][0]);
                acc[c][1] = fmaf(u, h4.y, acc[c][1]);
                acc[c][2] = fmaf(u, h4.z, acc[c][2]);
                acc[c][3] = fmaf(u, h4.w, acc[c][3]);
            }
        }

#pragma unroll
        for (int c = 0; c < 8; ++c)
#pragma unroll
            for (int q = 0; q < 4; ++q)
                red[c][bgrp * 4 + q][ks] = acc[c][q];
        __syncthreads();

        // reduce 16 k-slices for outputs o=tid and o=tid+128
        float z1 = xv1, z2 = xv2;
#pragma unroll
        for (int q = 0; q < 16; ++q) z1 += red[c1][bb][q];
#pragma unroll
        for (int q = 0; q < 16; ++q) z2 += red[c1 + 4][bb][q];
        z_s[c1][bb] = z1;
        z_s[c1 + 4][bb] = z2;
        __syncthreads();

        if (tid < 64) {
            float zf = z_s[0 + dd][bb];
            float zi = z_s[2 + dd][bb];
            float zc = z_s[4 + dd][bb];
            float zo = z_s[6 + dd][bb];
            float f  = sigmoidf_(zf);
            float ii = sigmoidf_(zi);
            float gg = tanhf(zc);
            float oo = sigmoidf_(zo);
            cstate = fmaf(f, cstate, ii * gg);
            float hh = oo * tanhf(cstate);
            int dim = cta * 2 + dd;
            g_hbuf[t & 1][dim * B + bb] = hh;
            out[(size_t)bb * (S * H) + (size_t)t * H + dim] = hh;
            if (t == S - 1) {
                size_t base = (size_t)B * S * H;
                if ((size_t)out_size >= base + 2 * (size_t)B * H) {
                    out[base + (size_t)bb * H + dim] = hh;                 // h_t
                    out[base + (size_t)B * H + (size_t)bb * H + dim] = cstate; // c_t
                }
            }
        }
        __syncthreads();
        if (tid == 0) {
            __threadfence();                  // release h writes
            atomicAdd(&g_ctr[t], 1u);
        }
    }
}

extern "C" void kernel_launch(void* const* d_in, const int* in_sizes, int n_in,
                              void* d_out, int out_size) {
    (void)in_sizes; (void)n_in;
    const float* x  = (const float*)d_in[0];
    const float* Wf = (const float*)d_in[1];
    const float* Uf = (const float*)d_in[2];
    const float* bf = (const float*)d_in[3];
    const float* Wi = (const float*)d_in[4];
    const float* Ui = (const float*)d_in[5];
    const float* bi = (const float*)d_in[6];
    const float* Wo = (const float*)d_in[7];
    const float* Uo = (const float*)d_in[8];
    const float* bo = (const float*)d_in[9];
    const float* Wc = (const float*)d_in[10];
    const float* Uc = (const float*)d_in[11];
    const float* bc = (const float*)d_in[12];

    pack_kernel<<<1024, 256>>>(Wf, Wi, Wc, Wo, Uf, Ui, Uc, Uo, bf, bi, bc, bo);
    gemm_xg_kernel<<<dim3(G4 / BN, (S * B) / BM), 256>>>(x);
    lstm_kernel<<<NCTA, NTHR>>>((float*)d_out, out_size);
}

// round 4
// speedup vs baseline: 1.0623x; 1.0623x over previous
#include <cuda_runtime.h>
#include <cstdint>

#define S 2048
#define B 32
#define I 256
#define H 256
#define G4 1024
#define NCTA 128
#define NTHR 128

// Static device scratch (no cudaMalloc allowed).
__device__ float g_Wp[I * G4];                 // packed/permuted input weights  [k][colp]
__device__ float g_Up[H * G4];                 // packed/permuted recurrent wts  [k][colp]
__device__ float g_bp[G4];                     // packed bias
__device__ float g_xg[(size_t)S * B * G4];     // precomputed input projections [t][b][colp]  (256 MB)
__device__ float g_hbuf[2][H * B];             // ping-pong h broadcast  [parity][dim][b]
__device__ unsigned g_ctr[S];                  // per-step arrival counters

// colp = cta*8 + g*2 + dd  maps to gate g in {f,i,c,o} and hidden dim j = 2*cta + dd
__global__ void pack_kernel(
    const float* __restrict__ Wf, const float* __restrict__ Wi,
    const float* __restrict__ Wc, const float* __restrict__ Wo,
    const float* __restrict__ Uf, const float* __restrict__ Ui,
    const float* __restrict__ Uc, const float* __restrict__ Uo,
    const float* __restrict__ bf, const float* __restrict__ bi,
    const float* __restrict__ bc, const float* __restrict__ bo)
{
    int idx = blockIdx.x * blockDim.x + threadIdx.x;
    if (idx < I * G4) {
        int k    = idx >> 10;
        int colp = idx & 1023;
        int g    = (colp >> 1) & 3;
        int j    = ((colp >> 3) << 1) | (colp & 1);
        const float* W = (g == 0) ? Wf : (g == 1) ? Wi : (g == 2) ? Wc : Wo;
        const float* U = (g == 0) ? Uf : (g == 1) ? Ui : (g == 2) ? Uc : Uo;
        g_Wp[idx] = W[k * H + j];
        g_Up[idx] = U[k * H + j];
        if (k == 0) {
            const float* bv = (g == 0) ? bf : (g == 1) ? bi : (g == 2) ? bc : bo;
            g_bp[colp] = bv[j];
        }
    }
    if (idx < 2 * H * B) ((float*)g_hbuf)[idx] = 0.f;
    if (idx < S) g_ctr[idx] = 0u;
}

// ---------------- Phase 1: xg[t][b][colp] = x[b][t][:] @ Wp + bp ----------------
#define BM 64
#define BN 64
#define BK 16

__global__ __launch_bounds__(256) void gemm_xg_kernel(const float* __restrict__ x)
{
    __shared__ float As[BK][BM + 4];   // transposed A tile, padded
    __shared__ float Bs[BK][BN];

    int tid = threadIdx.x;
    int r0 = blockIdx.y * BM;   // rows r = t*B + b
    int c0 = blockIdx.x * BN;
    int tr = tid >> 4, tc = tid & 15;

    int aRow = tid >> 2;
    int aK   = (tid & 3) << 2;
    int bK   = tid >> 4;
    int bC   = (tid & 15) << 2;

    int r  = r0 + aRow;
    int bb = r & 31;
    int tt = r >> 5;
    const float* aptr = x + ((size_t)bb * S + tt) * I + aK;

    float acc[4][4];
#pragma unroll
    for (int i2 = 0; i2 < 4; ++i2)
#pragma unroll
        for (int j2 = 0; j2 < 4; ++j2) acc[i2][j2] = 0.f;

    for (int k0 = 0; k0 < I; k0 += BK) {
        float4 av = *(const float4*)(aptr + k0);
        As[aK + 0][aRow] = av.x;
        As[aK + 1][aRow] = av.y;
        As[aK + 2][aRow] = av.z;
        As[aK + 3][aRow] = av.w;
        float4 bv = *(const float4*)(g_Wp + (size_t)(k0 + bK) * G4 + c0 + bC);
        *(float4*)&Bs[bK][bC] = bv;
        __syncthreads();
#pragma unroll
        for (int kk = 0; kk < BK; ++kk) {
            float4 a4 = *(const float4*)&As[kk][tr << 2];
            float4 b4 = *(const float4*)&Bs[kk][tc << 2];
            acc[0][0] = fmaf(a4.x, b4.x, acc[0][0]);
            acc[0][1] = fmaf(a4.x, b4.y, acc[0][1]);
            acc[0][2] = fmaf(a4.x, b4.z, acc[0][2]);
            acc[0][3] = fmaf(a4.x, b4.w, acc[0][3]);
            acc[1][0] = fmaf(a4.y, b4.x, acc[1][0]);
            acc[1][1] = fmaf(a4.y, b4.y, acc[1][1]);
            acc[1][2] = fmaf(a4.y, b4.z, acc[1][2]);
            acc[1][3] = fmaf(a4.y, b4.w, acc[1][3]);
            acc[2][0] = fmaf(a4.z, b4.x, acc[2][0]);
            acc[2][1] = fmaf(a4.z, b4.y, acc[2][1]);
            acc[2][2] = fmaf(a4.z, b4.z, acc[2][2]);
            acc[2][3] = fmaf(a4.z, b4.w, acc[2][3]);
            acc[3][0] = fmaf(a4.w, b4.x, acc[3][0]);
            acc[3][1] = fmaf(a4.w, b4.y, acc[3][1]);
            acc[3][2] = fmaf(a4.w, b4.z, acc[3][2]);
            acc[3][3] = fmaf(a4.w, b4.w, acc[3][3]);
        }
        __syncthreads();
    }

    float4 bias = *(const float4*)&g_bp[c0 + (tc << 2)];
#pragma unroll
    for (int i2 = 0; i2 < 4; ++i2) {
        int rr = r0 + (tr << 2) + i2;
        float4 o;
        o.x = acc[i2][0] + bias.x;
        o.y = acc[i2][1] + bias.y;
        o.z = acc[i2][2] + bias.z;
        o.w = acc[i2][3] + bias.w;
        *(float4*)(g_xg + (size_t)rr * G4 + c0 + (tc << 2)) = o;
    }
}

// ---------------- Phase 2: persistent recurrence ----------------
__device__ __forceinline__ float sigmoidf_(float v) {
    return 1.f / (1.f + __expf(-v));
}

__global__ __launch_bounds__(NTHR, 1) void lstm_kernel(float* __restrict__ out, int out_size)
{
    int cta = blockIdx.x;
    int tid = threadIdx.x;
    int bgrp = tid >> 4;     // 0..7 -> batches 4*bgrp..+3
    int ks   = tid & 15;     // k-slice: k = it*16 + ks

    __shared__ float U_s[8][H];        // [c][k], c = local gate col
    __shared__ float red[8][32][17];   // partials [c][b][ks], padded (stride 17 -> conflict-free)
    __shared__ float z_s[8][32];

    for (int i = tid; i < 8 * H; i += NTHR) {
        int c = i >> 8, k = i & 255;
        U_s[c][k] = g_Up[(size_t)k * G4 + cta * 8 + c];
    }

    int dd = tid >> 5;       // for update threads (tid<64)
    int bb = tid & 31;
    int c1 = tid >> 5;       // for reduction outputs o=tid, o=tid+128
    float cstate = 0.f;
    __syncthreads();

    for (int t = 0; t < S; ++t) {
        if (t > 0) {
            if (tid == 0) {
                volatile unsigned* p = &g_ctr[t - 1];
                while (*p < NCTA) {}
                __threadfence();   // acquire: order subsequent h loads after observed release
            }
            __syncthreads();
        }

        // prefetch this step's input projections (1 sector per batch row)
        const float* xgp = g_xg + (size_t)t * (B * G4) + cta * 8;
        float xv1 = __ldg(xgp + (size_t)bb * G4 + c1);
        float xv2 = __ldg(xgp + (size_t)bb * G4 + c1 + 4);

        // prefetch h_{t-1} (bypass L1: incoherent across SMs)
        const float4* hb = (const float4*)g_hbuf[(t + 1) & 1];
        float4 hv[16];
#pragma unroll
        for (int it = 0; it < 16; ++it)
            hv[it] = __ldcg(hb + (size_t)(it * 16 + ks) * 8 + bgrp);

        float acc[8][4];
#pragma unroll
        for (int c = 0; c < 8; ++c)
#pragma unroll
            for (int q = 0; q < 4; ++q) acc[c][q] = 0.f;

#pragma unroll
        for (int it = 0; it < 16; ++it) {
            int k = it * 16 + ks;
            float4 h4 = hv[it];
#pragma unroll
            for (int c = 0; c < 8; ++c) {
                float u = U_s[c][k];
                acc[c][0] = fmaf(u, h4.x, acc[c][0]);
                acc[c][1] = fmaf(u, h4.y, acc[c][1]);
                acc[c][2] = fmaf(u, h4.z, acc[c][2]);
                acc[c][3] = fmaf(u, h4.w, acc[c][3]);
            }
        }

#pragma unroll
        for (int c = 0; c < 8; ++c)
#pragma unroll
            for (int q = 0; q < 4; ++q)
                red[c][bgrp * 4 + q][ks] = acc[c][q];
        __syncthreads();

        // reduce 16 k-slices for outputs o=tid and o=tid+128
        float z1 = xv1, z2 = xv2;
#pragma unroll
        for (int q = 0; q < 16; ++q) z1 += red[c1][bb][q];
#pragma unroll
        for (int q = 0; q < 16; ++q) z2 += red[c1 + 4][bb][q];
        z_s[c1][bb] = z1;
        z_s[c1 + 4][bb] = z2;
        __syncthreads();

        if (tid < 64) {
            float zf = z_s[0 + dd][bb];
            float zi = z_s[2 + dd][bb];
            float zc = z_s[4 + dd][bb];
            float zo = z_s[6 + dd][bb];
            float f  = sigmoidf_(zf);
            float ii = sigmoidf_(zi);
            float gg = tanhf(zc);
            float oo = sigmoidf_(zo);
            cstate = fmaf(f, cstate, ii * gg);
            float hh = oo * tanhf(cstate);
            int dim = cta * 2 + dd;
            g_hbuf[t & 1][dim * B + bb] = hh;
            out[(size_t)bb * (S * H) + (size_t)t * H + dim] = hh;
            if (t == S - 1) {
                size_t base = (size_t)B * S * H;
                if ((size_t)out_size >= base + 2 * (size_t)B * H) {
                    out[base + (size_t)bb * H + dim] = hh;                 // h_t
                    out[base + (size_t)B * H + (size_t)bb * H + dim] = cstate; // c_t
                }
            }
        }
        __syncthreads();
        if (tid == 0) {
            __threadfence();                  // release h writes
            atomicAdd(&g_ctr[t], 1u);
        }
    }
}

extern "C" void kernel_launch(void* const* d_in, const int* in_sizes, int n_in,
                              void* d_out, int out_size) {
    (void)in_sizes; (void)n_in;
    const float* x  = (const float*)d_in[0];
    const float* Wf = (const float*)d_in[1];
    const float* Uf = (const float*)d_in[2];
    const float* bf = (const float*)d_in[3];
    const float* Wi = (const float*)d_in[4];
    const float* Ui = (const float*)d_in[5];
    const float* bi = (const float*)d_in[6];
    const float* Wo = (const float*)d_in[7];
    const float* Uo = (const float*)d_in[8];
    const float* bo = (const float*)d_in[9];
    const float* Wc = (const float*)d_in[10];
    const float* Uc = (const float*)d_in[11];
    const float* bc = (const float*)d_in[12];

    pack_kernel<<<1024, 256>>>(Wf, Wi, Wc, Wo, Uf, Ui, Uc, Uo, bf, bi, bc, bo);
    gemm_xg_kernel<<<dim3(G4 / BN, (S * B) / BM), 256>>>(x);
    lstm_kernel<<<NCTA, NTHR>>>((float*)d_out, out_size);
}